// round 7
// baseline (speedup 1.0000x reference)
#include <cuda_runtime.h>
#include <cuda_bf16.h>
#include <math.h>
#include <stdint.h>

typedef __nv_bfloat16 bf16;

// ---------------------------------------------------------------------------
// HiLoAttention: B=8, N=4096 (64x64), C=512, heads=8, hd=64, window=2
//   prep (pool+window fused) -> bf16 hi/lo rows [40960,512]
//   gemm_mma mode1 -> hi rows: split q/k/v arrays; lo rows: qcat fp32
//   hi_attn_mma (HMMA flash), lo_attn, upsample+add -> bf16 hi/lo [32768,512]
//   gemm_mma mode0 + bias -> out
//   Round 7: 3-stage cp.async ring + single barrier per chunk (GEMM + attn)
// ---------------------------------------------------------------------------

__device__ bf16  g_Ahi[40960ull * 512];
__device__ bf16  g_Alo[40960ull * 512];
__device__ bf16  g_Wqh[1536 * 512];
__device__ bf16  g_Wql[1536 * 512];
__device__ bf16  g_Wph[512 * 512];
__device__ bf16  g_Wpl[512 * 512];
__device__ float g_qcat[40960ull * 1536];
__device__ float g_ahi[8 * 1024 * 512];
__device__ float g_acc[8 * 4096 * 512];
__device__ bf16  g_Phi[32768ull * 512];
__device__ bf16  g_Plo[32768ull * 512];
__device__ bf16  g_Qh[8 * 8 * 1024 * 64];
__device__ bf16  g_Ql[8 * 8 * 1024 * 64];
__device__ bf16  g_Kh[8 * 8 * 1024 * 64];
__device__ bf16  g_Kl[8 * 8 * 1024 * 64];
__device__ bf16  g_Vh[8 * 8 * 1024 * 64];
__device__ bf16  g_Vl[8 * 8 * 1024 * 64];

// ------------------------------ helpers -------------------------------------
__device__ __forceinline__ uint32_t smem_u32(const void* p) {
    uint32_t a;
    asm("{ .reg .u64 t; cvta.to.shared.u64 t, %1; cvt.u32.u64 %0, t; }"
        : "=r"(a) : "l"(p));
    return a;
}
__device__ __forceinline__ void cp16(uint32_t dst, const void* src) {
    asm volatile("cp.async.cg.shared.global [%0], [%1], 16;"
                 :: "r"(dst), "l"(src) : "memory");
}
__device__ __forceinline__ uint32_t sw128(uint32_t off) {
    return off ^ ((off >> 3) & 0x70);
}
__device__ __forceinline__ void pack_split(float p0, float p1,
                                           uint32_t* hi, uint32_t* lo) {
    __nv_bfloat162 h2 = __floats2bfloat162_rn(p0, p1);
    float2 f = __bfloat1622float2(h2);
    __nv_bfloat162 l2 = __floats2bfloat162_rn(p0 - f.x, p1 - f.y);
    *hi = *(uint32_t*)&h2;
    *lo = *(uint32_t*)&l2;
}
__device__ __forceinline__ void split4_store(float4 v, bf16* H, bf16* L,
                                             size_t off) {
    uint32_t h01, l01, h23, l23;
    pack_split(v.x, v.y, &h01, &l01);
    pack_split(v.z, v.w, &h23, &l23);
    *(uint2*)(H + off) = make_uint2(h01, h23);
    *(uint2*)(L + off) = make_uint2(l01, l23);
}

#define LDSM4(r, addr)                                                        \
    asm volatile("ldmatrix.sync.aligned.m8n8.x4.shared.b16 {%0,%1,%2,%3}, [%4];" \
                 : "=r"((r)[0]), "=r"((r)[1]), "=r"((r)[2]), "=r"((r)[3])     \
                 : "r"(addr))

#define LDSM4T(r, addr)                                                       \
    asm volatile("ldmatrix.sync.aligned.m8n8.x4.trans.shared.b16 {%0,%1,%2,%3}, [%4];" \
                 : "=r"((r)[0]), "=r"((r)[1]), "=r"((r)[2]), "=r"((r)[3])     \
                 : "r"(addr))

#define MMA16816(c, a, b0, b1)                                                \
    asm volatile("mma.sync.aligned.m16n8k16.row.col.f32.bf16.bf16.f32 "       \
                 "{%0,%1,%2,%3},{%4,%5,%6,%7},{%8,%9},{%0,%1,%2,%3};"         \
                 : "+f"((c)[0]), "+f"((c)[1]), "+f"((c)[2]), "+f"((c)[3])     \
                 : "r"((a)[0]), "r"((a)[1]), "r"((a)[2]), "r"((a)[3]),        \
                   "r"(b0), "r"(b1))

// ------------------- fused pool + window (block per (b,w)) -------------------
__global__ __launch_bounds__(128) void prep_kernel(const float* __restrict__ x,
                                                   bf16* __restrict__ Ahi,
                                                   bf16* __restrict__ Alo) {
    __shared__ float xs[4][512];
    const int w = blockIdx.x & 1023, b = blockIdx.x >> 10;
    const int hh = w >> 5, wh = w & 31;
    const int tid = threadIdx.x;
    const int tok0 = (hh * 2) * 64 + wh * 2;
    const float* xb = x + ((size_t)b * 4096) * 512;
    const int toks[4] = {tok0, tok0 + 1, tok0 + 64, tok0 + 65};
#pragma unroll
    for (int s = 0; s < 4; ++s) {
        const float4* src = (const float4*)(xb + (size_t)toks[s] * 512);
        *(float4*)&xs[s][tid * 4] = src[tid];
    }
    __syncthreads();
    {
        int c = tid * 4;
        float4 a = *(float4*)&xs[0][c];
        float4 b2 = *(float4*)&xs[1][c];
        float4 c2 = *(float4*)&xs[2][c];
        float4 d2 = *(float4*)&xs[3][c];
        float4 v = {0.25f * (a.x + b2.x + c2.x + d2.x),
                    0.25f * (a.y + b2.y + c2.y + d2.y),
                    0.25f * (a.z + b2.z + c2.z + d2.z),
                    0.25f * (a.w + b2.w + c2.w + d2.w)};
        split4_store(v, Ahi, Alo, (size_t)(b * 1024 + w) * 512 + c);
    }
#pragma unroll
    for (int t = 0; t < 4; ++t) {
        int u = tid;
        float4 v = {xs[0][t * 128 + u], xs[1][t * 128 + u],
                    xs[2][t * 128 + u], xs[3][t * 128 + u]};
        size_t wrow = (size_t)(8192 + (b * 1024 + w) * 4 + t) * 512;
        split4_store(v, Ahi, Alo, wrow + u * 4);
    }
}

// ------------------------ weight split (vectorized) --------------------------
__global__ __launch_bounds__(256) void split_kernel(const float* __restrict__ src,
                                                    bf16* __restrict__ hi,
                                                    bf16* __restrict__ lo, int n4) {
    int g = blockIdx.x * 256 + threadIdx.x;
    if (g >= n4) return;
    float4 v = ((const float4*)src)[g];
    split4_store(v, hi, lo, (size_t)g * 4);
}

// --------------- HMMA bf16x3 GEMM (K=512), 4 warps, 64x64 warp tile ----------
// 3-stage cp.async ring, one barrier per chunk.
#define GEMM_SMEM (3 * 32768 + 1024)

__global__ __launch_bounds__(128) void gemm_mma(
    const bf16* __restrict__ Ah, const bf16* __restrict__ Al,
    const bf16* __restrict__ Bh, const bf16* __restrict__ Bl,
    const float* __restrict__ bias, float* __restrict__ C, int N, int mode,
    bf16* __restrict__ Qh, bf16* __restrict__ Ql,
    bf16* __restrict__ Kh, bf16* __restrict__ Kl,
    bf16* __restrict__ Vh, bf16* __restrict__ Vl) {
    extern __shared__ char dynsm[];
    const int tid = threadIdx.x;
    const int wid = tid >> 5, lane = tid & 31;
    const int wm = wid & 1, wn = wid >> 1;
    const size_t bm = (size_t)blockIdx.y * 128;
    const size_t bn = (size_t)blockIdx.x * 128;
    const uint32_t sb = (smem_u32(dynsm) + 1023) & ~1023u;

    const char* srcs[4] = {(const char*)(Ah + bm * 512),
                           (const char*)(Al + bm * 512),
                           (const char*)(Bh + bn * 512),
                           (const char*)(Bl + bn * 512)};

    auto load_chunk = [&](int kc, int s) {
        const uint32_t base = sb + s * 32768;
#pragma unroll
        for (int mat = 0; mat < 4; ++mat) {
#pragma unroll
            for (int j = 0; j < 4; ++j) {
                uint32_t u = tid + j * 128;
                uint32_t r = u >> 2, c16 = u & 3;
                cp16(base + mat * 8192 + sw128(u * 16),
                     srcs[mat] + (size_t)r * 1024 + kc * 64 + c16 * 16);
            }
        }
        asm volatile("cp.async.commit_group;" ::: "memory");
    };

    float c[4][8][4];
#pragma unroll
    for (int i = 0; i < 4; ++i)
#pragma unroll
        for (int j = 0; j < 8; ++j)
#pragma unroll
            for (int q = 0; q < 4; ++q) c[i][j][q] = 0.f;

    const int sub = lane >> 3;
    const int rowl = ((sub & 1) << 3) + (lane & 7);
    const int csel = sub >> 1;

    load_chunk(0, 0);
    load_chunk(1, 1);

#pragma unroll 1
    for (int kc = 0; kc < 16; ++kc) {
        const int s = kc % 3;
        if (kc < 15) asm volatile("cp.async.wait_group 1;" ::: "memory");
        else         asm volatile("cp.async.wait_group 0;" ::: "memory");
        __syncthreads();
        // issue next load FIRST (into stage freed at kc-1), then consume
        if (kc + 2 < 16) load_chunk(kc + 2, (kc + 2) % 3);
        const uint32_t st = sb + s * 32768;

#pragma unroll
        for (int kk = 0; kk < 2; ++kk) {
            uint32_t bh4[2][4], bl4[2][4];
            {
                uint32_t off = (uint32_t)(wn * 64 + rowl) * 64 +
                               (uint32_t)(kk * 2 + csel) * 16;
                LDSM4(bh4[0], st + 16384 + sw128(off));
                LDSM4(bl4[0], st + 24576 + sw128(off));
            }
            uint32_t ah[4][4], al[4][4];
#pragma unroll
            for (int mt = 0; mt < 4; ++mt) {
                uint32_t off = (uint32_t)(wm * 64 + mt * 16 + rowl) * 64 +
                               (uint32_t)(kk * 2 + csel) * 16;
                LDSM4(ah[mt], st + sw128(off));
                LDSM4(al[mt], st + 8192 + sw128(off));
            }
#pragma unroll
            for (int nb = 0; nb < 4; ++nb) {
                const int p = nb & 1;
                if (nb < 3) {
                    uint32_t off = (uint32_t)(wn * 64 + (nb + 1) * 16 + rowl) * 64 +
                                   (uint32_t)(kk * 2 + csel) * 16;
                    LDSM4(bh4[p ^ 1], st + 16384 + sw128(off));
                    LDSM4(bl4[p ^ 1], st + 24576 + sw128(off));
                }
#pragma unroll
                for (int mt = 0; mt < 4; ++mt) {
                    MMA16816(c[mt][nb * 2], ah[mt], bh4[p][0], bh4[p][2]);
                    MMA16816(c[mt][nb * 2 + 1], ah[mt], bh4[p][1], bh4[p][3]);
                }
#pragma unroll
                for (int mt = 0; mt < 4; ++mt) {
                    MMA16816(c[mt][nb * 2], ah[mt], bl4[p][0], bl4[p][2]);
                    MMA16816(c[mt][nb * 2 + 1], ah[mt], bl4[p][1], bl4[p][3]);
                }
#pragma unroll
                for (int mt = 0; mt < 4; ++mt) {
                    MMA16816(c[mt][nb * 2], al[mt], bh4[p][0], bh4[p][2]);
                    MMA16816(c[mt][nb * 2 + 1], al[mt], bh4[p][1], bh4[p][3]);
                }
            }
        }
    }

    const int r0 = lane >> 2;
    const int c0 = (lane & 3) * 2;
    if (mode == 1 && bm < 8192) {
#pragma unroll
        for (int mt = 0; mt < 4; ++mt)
#pragma unroll
            for (int n8 = 0; n8 < 8; ++n8) {
                int col = (int)bn + wn * 64 + n8 * 8 + c0;
                int which = col >> 9, jj = col & 511;
                int h = jj >> 6, d = jj & 63;
                bf16* H = which == 0 ? Qh : (which == 1 ? Kh : Vh);
                bf16* L = which == 0 ? Ql : (which == 1 ? Kl : Vl);
                float sc = which == 0 ? 0.125f : 1.0f;
#pragma unroll
                for (int half = 0; half < 2; ++half) {
                    int row = (int)bm + wm * 64 + mt * 16 + r0 + half * 8;
                    int b = row >> 10, tok = row & 1023;
                    size_t dst = ((size_t)((b * 8 + h) * 1024 + tok)) * 64 + d;
                    uint32_t hu, lu;
                    pack_split(c[mt][n8][half * 2] * sc,
                               c[mt][n8][half * 2 + 1] * sc, &hu, &lu);
                    *(uint32_t*)(H + dst) = hu;
                    *(uint32_t*)(L + dst) = lu;
                }
            }
    } else {
#pragma unroll
        for (int mt = 0; mt < 4; ++mt)
#pragma unroll
            for (int n8 = 0; n8 < 8; ++n8) {
                size_t row = bm + wm * 64 + mt * 16 + r0;
                size_t col = bn + wn * 64 + n8 * 8 + c0;
                float bx = 0.f, by = 0.f;
                if (bias) { bx = bias[col]; by = bias[col + 1]; }
                float2 v0 = {c[mt][n8][0] + bx, c[mt][n8][1] + by};
                float2 v1 = {c[mt][n8][2] + bx, c[mt][n8][3] + by};
                *(float2*)(C + row * (size_t)N + col) = v0;
                *(float2*)(C + (row + 8) * (size_t)N + col) = v1;
            }
    }
}

// ------------------- HMMA flash attention (hi branch) ------------------------
// 3-stage KV ring, one barrier per tile.
#define ATT_SMEM (3 * 32768 + 1024)

__global__ __launch_bounds__(128) void hi_attn_mma(
    const bf16* __restrict__ Qh, const bf16* __restrict__ Ql,
    const bf16* __restrict__ Kh, const bf16* __restrict__ Kl,
    const bf16* __restrict__ Vh, const bf16* __restrict__ Vl,
    float* __restrict__ out) {
    extern __shared__ char dynsm[];
    const int tid = threadIdx.x;
    const int wid = tid >> 5, lane = tid & 31;
    const int qt = blockIdx.x, h = blockIdx.y, b = blockIdx.z;
    const uint32_t sb = (smem_u32(dynsm) + 1023) & ~1023u;
    const size_t bh = (size_t)(b * 8 + h) * 65536;

    const int sub = lane >> 3;
    const int rowl = ((sub & 1) << 3) + (lane & 7);
    const int csel = sub >> 1;

    {
        const char* qh_src = (const char*)(Qh + bh + (size_t)qt * 64 * 64);
        const char* ql_src = (const char*)(Ql + bh + (size_t)qt * 64 * 64);
#pragma unroll
        for (int u = tid; u < 512; u += 128) {
            cp16(sb + sw128(u * 16), qh_src + u * 16);
            cp16(sb + 8192 + sw128(u * 16), ql_src + u * 16);
        }
        asm volatile("cp.async.commit_group;" ::: "memory");
        asm volatile("cp.async.wait_group 0;" ::: "memory");
        __syncthreads();
    }
    uint32_t qh[4][4], ql[4][4];
#pragma unroll
    for (int kf = 0; kf < 4; ++kf) {
        uint32_t off = (uint32_t)(wid * 16 + rowl) * 128 + kf * 32 + csel * 16;
        LDSM4(qh[kf], sb + sw128(off));
        LDSM4(ql[kf], sb + 8192 + sw128(off));
    }
    __syncthreads();

    const char* kh_src = (const char*)(Kh + bh);
    const char* kl_src = (const char*)(Kl + bh);
    const char* vh_src = (const char*)(Vh + bh);
    const char* vl_src = (const char*)(Vl + bh);

    auto load_kv = [&](int kt, int s) {
        const uint32_t base = sb + s * 32768;
        const size_t go = (size_t)kt * 8192;
#pragma unroll
        for (int u = tid; u < 512; u += 128) {
            uint32_t sw = sw128(u * 16);
            cp16(base + sw, kh_src + go + u * 16);
            cp16(base + 8192 + sw, kl_src + go + u * 16);
            cp16(base + 16384 + sw, vh_src + go + u * 16);
            cp16(base + 24576 + sw, vl_src + go + u * 16);
        }
        asm volatile("cp.async.commit_group;" ::: "memory");
    };

    load_kv(0, 0);
    load_kv(1, 1);

    float o[8][4];
#pragma unroll
    for (int i = 0; i < 8; ++i)
#pragma unroll
        for (int j = 0; j < 4; ++j) o[i][j] = 0.f;
    float m0 = -1e30f, m1 = -1e30f, l0 = 0.f, l1 = 0.f;

#pragma unroll 1
    for (int kt = 0; kt < 16; ++kt) {
        const int s = kt % 3;
        if (kt < 15) asm volatile("cp.async.wait_group 1;" ::: "memory");
        else         asm volatile("cp.async.wait_group 0;" ::: "memory");
        __syncthreads();
        if (kt + 2 < 16) load_kv(kt + 2, (kt + 2) % 3);
        const uint32_t base = sb + s * 32768;

        float sfr[8][4];
#pragma unroll
        for (int i = 0; i < 8; ++i)
#pragma unroll
            for (int j = 0; j < 4; ++j) sfr[i][j] = 0.f;

#pragma unroll
        for (int kf = 0; kf < 4; ++kf) {
            uint32_t kbh[4][4], kbl[4][4];
#pragma unroll
            for (int nb = 0; nb < 4; ++nb) {
                uint32_t off = (uint32_t)(nb * 16 + rowl) * 128 + kf * 32 + csel * 16;
                LDSM4(kbh[nb], base + sw128(off));
                LDSM4(kbl[nb], base + 8192 + sw128(off));
            }
#pragma unroll
            for (int nb = 0; nb < 4; ++nb) {
                MMA16816(sfr[nb * 2], qh[kf], kbh[nb][0], kbh[nb][2]);
                MMA16816(sfr[nb * 2 + 1], qh[kf], kbh[nb][1], kbh[nb][3]);
            }
#pragma unroll
            for (int nb = 0; nb < 4; ++nb) {
                MMA16816(sfr[nb * 2], qh[kf], kbl[nb][0], kbl[nb][2]);
                MMA16816(sfr[nb * 2 + 1], qh[kf], kbl[nb][1], kbl[nb][3]);
            }
#pragma unroll
            for (int nb = 0; nb < 4; ++nb) {
                MMA16816(sfr[nb * 2], ql[kf], kbh[nb][0], kbh[nb][2]);
                MMA16816(sfr[nb * 2 + 1], ql[kf], kbh[nb][1], kbh[nb][3]);
            }
        }

        float mx0 = -1e30f, mx1 = -1e30f;
#pragma unroll
        for (int n8 = 0; n8 < 8; ++n8) {
            mx0 = fmaxf(mx0, fmaxf(sfr[n8][0], sfr[n8][1]));
            mx1 = fmaxf(mx1, fmaxf(sfr[n8][2], sfr[n8][3]));
        }
        mx0 = fmaxf(mx0, __shfl_xor_sync(0xffffffffu, mx0, 1));
        mx0 = fmaxf(mx0, __shfl_xor_sync(0xffffffffu, mx0, 2));
        mx1 = fmaxf(mx1, __shfl_xor_sync(0xffffffffu, mx1, 1));
        mx1 = fmaxf(mx1, __shfl_xor_sync(0xffffffffu, mx1, 2));
        float m0n = fmaxf(m0, mx0), m1n = fmaxf(m1, mx1);
        float c0 = __expf(m0 - m0n), c1 = __expf(m1 - m1n);
        m0 = m0n; m1 = m1n;
        float s0 = 0.f, s1 = 0.f;
#pragma unroll
        for (int n8 = 0; n8 < 8; ++n8) {
            sfr[n8][0] = __expf(sfr[n8][0] - m0n);
            sfr[n8][1] = __expf(sfr[n8][1] - m0n);
            sfr[n8][2] = __expf(sfr[n8][2] - m1n);
            sfr[n8][3] = __expf(sfr[n8][3] - m1n);
            s0 += sfr[n8][0] + sfr[n8][1];
            s1 += sfr[n8][2] + sfr[n8][3];
        }
        s0 += __shfl_xor_sync(0xffffffffu, s0, 1);
        s0 += __shfl_xor_sync(0xffffffffu, s0, 2);
        s1 += __shfl_xor_sync(0xffffffffu, s1, 1);
        s1 += __shfl_xor_sync(0xffffffffu, s1, 2);
        l0 = l0 * c0 + s0;
        l1 = l1 * c1 + s1;
#pragma unroll
        for (int n8 = 0; n8 < 8; ++n8) {
            o[n8][0] *= c0; o[n8][1] *= c0;
            o[n8][2] *= c1; o[n8][3] *= c1;
        }

#pragma unroll
        for (int kf = 0; kf < 4; ++kf) {
            uint32_t ah4[4], al4[4];
            pack_split(sfr[2 * kf][0], sfr[2 * kf][1], &ah4[0], &al4[0]);
            pack_split(sfr[2 * kf][2], sfr[2 * kf][3], &ah4[1], &al4[1]);
            pack_split(sfr[2 * kf + 1][0], sfr[2 * kf + 1][1], &ah4[2], &al4[2]);
            pack_split(sfr[2 * kf + 1][2], sfr[2 * kf + 1][3], &ah4[3], &al4[3]);
            uint32_t vbh[4][4], vbl[4][4];
#pragma unroll
            for (int dd = 0; dd < 4; ++dd) {
                uint32_t off = (uint32_t)(kf * 16 + rowl) * 128 + dd * 32 + csel * 16;
                LDSM4T(vbh[dd], base + 16384 + sw128(off));
                LDSM4T(vbl[dd], base + 24576 + sw128(off));
            }
#pragma unroll
            for (int dd = 0; dd < 4; ++dd) {
                MMA16816(o[dd * 2], ah4, vbh[dd][0], vbh[dd][1]);
                MMA16816(o[dd * 2 + 1], ah4, vbh[dd][2], vbh[dd][3]);
            }
#pragma unroll
            for (int dd = 0; dd < 4; ++dd) {
                MMA16816(o[dd * 2], ah4, vbl[dd][0], vbl[dd][1]);
                MMA16816(o[dd * 2 + 1], ah4, vbl[dd][2], vbl[dd][3]);
            }
#pragma unroll
            for (int dd = 0; dd < 4; ++dd) {
                MMA16816(o[dd * 2], al4, vbh[dd][0], vbh[dd][1]);
                MMA16816(o[dd * 2 + 1], al4, vbh[dd][2], vbh[dd][3]);
            }
        }
    }

    float inv0 = 1.0f / l0, inv1 = 1.0f / l1;
    int r0 = lane >> 2, cc = (lane & 3) * 2;
    size_t row = (size_t)(b * 1024 + qt * 64 + wid * 16 + r0);
#pragma unroll
    for (int n8 = 0; n8 < 8; ++n8) {
        size_t col = h * 64 + n8 * 8 + cc;
        float2 v0 = {o[n8][0] * inv0, o[n8][1] * inv0};
        float2 v1 = {o[n8][2] * inv1, o[n8][3] * inv1};
        *(float2*)(out + row * 512 + col) = v0;
        *(float2*)(out + (row + 8) * 512 + col) = v1;
    }
}

// ----------------------------- lo attention ---------------------------------
__global__ __launch_bounds__(256) void lo_attn_kernel(const float* __restrict__ qkv,
                                                      float* __restrict__ acc) {
    int gw = (blockIdx.x * 256 + threadIdx.x) >> 5;
    int lane = threadIdx.x & 31;
    int h = gw & 7;
    int w = (gw >> 3) & 1023;
    int b = gw >> 13;
    const float* base = qkv + (size_t)(b * 4096 + w * 4) * 1536 + h * 64 + lane;
    float q[4][2], k[4][2], v[4][2];
#pragma unroll
    for (int t = 0; t < 4; ++t) {
        const float* r = base + t * 1536;
        q[t][0] = r[0];    q[t][1] = r[32];
        k[t][0] = r[512];  k[t][1] = r[544];
        v[t][0] = r[1024]; v[t][1] = r[1056];
    }
    float lg[4][4];
#pragma unroll
    for (int t = 0; t < 4; ++t)
#pragma unroll
        for (int s2 = 0; s2 < 4; ++s2)
            lg[t][s2] = q[t][0] * k[s2][0] + q[t][1] * k[s2][1];
#pragma unroll
    for (int off = 16; off; off >>= 1)
#pragma unroll
        for (int t = 0; t < 4; ++t)
#pragma unroll
            for (int s2 = 0; s2 < 4; ++s2)
                lg[t][s2] += __shfl_xor_sync(0xffffffffu, lg[t][s2], off);

    int hh = w >> 5, wh = w & 31;
#pragma unroll
    for (int t = 0; t < 4; ++t) {
        float L0 = lg[t][0] * 0.125f, L1 = lg[t][1] * 0.125f;
        float L2 = lg[t][2] * 0.125f, L3 = lg[t][3] * 0.125f;
        float m = fmaxf(fmaxf(L0, L1), fmaxf(L2, L3));
        float p0 = __expf(L0 - m), p1 = __expf(L1 - m);
        float p2 = __expf(L2 - m), p3 = __expf(L3 - m);
        float inv = 1.0f / (p0 + p1 + p2 + p3);
        float o0 = (p0 * v[0][0] + p1 * v[1][0] + p2 * v[2][0] + p3 * v[3][0]) * inv;
        float o1 = (p0 * v[0][1] + p1 * v[1][1] + p2 * v[2][1] + p3 * v[3][1]) * inv;
        int tok = (hh * 2 + (t >> 1)) * 64 + wh * 2 + (t & 1);
        float* op = acc + (size_t)(b * 4096 + tok) * 512 + h * 64 + lane;
        op[0] = o0;
        op[32] = o1;
    }
}

// --------- bilinear upsample + add -> bf16 hi/lo split (vectorized) ----------
__global__ __launch_bounds__(256) void upsample_add_kernel(const float* __restrict__ hi,
                                                           const float* __restrict__ acc,
                                                           bf16* __restrict__ ph,
                                                           bf16* __restrict__ pl) {
    int g = blockIdx.x * 256 + threadIdx.x;
    if (g >= 8 * 4096 * 128) return;
    int c = (g & 127) * 4;
    int tok = (g >> 7) & 4095;
    int b = g >> 19;
    int y = tok >> 6, x = tok & 63;
    float fy = 0.5f * y - 0.25f;
    float fx = 0.5f * x - 0.25f;
    int y0 = (int)floorf(fy);
    int x0 = (int)floorf(fx);
    float wy = fy - (float)y0;
    float wx = fx - (float)x0;
    int y0c = max(y0, 0), y1c = min(y0 + 1, 31);
    int x0c = max(x0, 0), x1c = min(x0 + 1, 31);
    const float* hp = hi + (size_t)b * 1024 * 512 + c;
    float4 v00 = *(const float4*)(hp + (size_t)(y0c * 32 + x0c) * 512);
    float4 v01 = *(const float4*)(hp + (size_t)(y0c * 32 + x1c) * 512);
    float4 v10 = *(const float4*)(hp + (size_t)(y1c * 32 + x0c) * 512);
    float4 v11 = *(const float4*)(hp + (size_t)(y1c * 32 + x1c) * 512);
    float w00 = (1.f - wy) * (1.f - wx), w01 = (1.f - wy) * wx;
    float w10 = wy * (1.f - wx), w11 = wy * wx;
    size_t idx = ((size_t)(b * 4096 + tok)) * 512 + c;
    float4 a = *(const float4*)(acc + idx);
    float4 r;
    r.x = a.x + w00 * v00.x + w01 * v01.x + w10 * v10.x + w11 * v11.x;
    r.y = a.y + w00 * v00.y + w01 * v01.y + w10 * v10.y + w11 * v11.y;
    r.z = a.z + w00 * v00.z + w01 * v01.z + w10 * v10.z + w11 * v11.z;
    r.w = a.w + w00 * v00.w + w01 * v01.w + w10 * v10.w + w11 * v11.w;
    split4_store(r, ph, pl, idx);
}

// --------------------------------- launch -----------------------------------
extern "C" void kernel_launch(void* const* d_in, const int* in_sizes, int n_in,
                              void* d_out, int out_size) {
    const float* x     = (const float*)d_in[0];
    const float* Wqkv  = (const float*)d_in[1];
    const float* Wproj = (const float*)d_in[2];
    const float* bproj = (const float*)d_in[3];
    float* out = (float*)d_out;

    bf16 *Ahi, *Alo, *Wqh, *Wql, *Wph, *Wpl, *Phi, *Plo;
    bf16 *Qh, *Ql, *Kh, *Kl, *Vh, *Vl;
    float *qcat, *ahi, *acc;
    cudaGetSymbolAddress((void**)&Ahi, g_Ahi);
    cudaGetSymbolAddress((void**)&Alo, g_Alo);
    cudaGetSymbolAddress((void**)&Wqh, g_Wqh);
    cudaGetSymbolAddress((void**)&Wql, g_Wql);
    cudaGetSymbolAddress((void**)&Wph, g_Wph);
    cudaGetSymbolAddress((void**)&Wpl, g_Wpl);
    cudaGetSymbolAddress((void**)&Phi, g_Phi);
    cudaGetSymbolAddress((void**)&Plo, g_Plo);
    cudaGetSymbolAddress((void**)&qcat, g_qcat);
    cudaGetSymbolAddress((void**)&ahi, g_ahi);
    cudaGetSymbolAddress((void**)&acc, g_acc);
    cudaGetSymbolAddress((void**)&Qh, g_Qh);
    cudaGetSymbolAddress((void**)&Ql, g_Ql);
    cudaGetSymbolAddress((void**)&Kh, g_Kh);
    cudaGetSymbolAddress((void**)&Kl, g_Kl);
    cudaGetSymbolAddress((void**)&Vh, g_Vh);
    cudaGetSymbolAddress((void**)&Vl, g_Vl);

    cudaFuncSetAttribute((const void*)gemm_mma,
                         cudaFuncAttributeMaxDynamicSharedMemorySize, GEMM_SMEM);
    cudaFuncSetAttribute((const void*)hi_attn_mma,
                         cudaFuncAttributeMaxDynamicSharedMemorySize, ATT_SMEM);

    prep_kernel<<<8192, 128>>>(x, Ahi, Alo);
    split_kernel<<<768, 256>>>(Wqkv, Wqh, Wql, 1536 * 512 / 4);
    split_kernel<<<256, 256>>>(Wproj, Wph, Wpl, 512 * 512 / 4);

    gemm_mma<<<dim3(12, 320), 128, GEMM_SMEM>>>(Ahi, Alo, Wqh, Wql, nullptr,
                                                qcat, 1536, 1,
                                                Qh, Ql, Kh, Kl, Vh, Vl);

    hi_attn_mma<<<dim3(16, 8, 8), 128, ATT_SMEM>>>(Qh, Ql, Kh, Kl, Vh, Vl, ahi);
    lo_attn_kernel<<<8192, 256>>>(qcat + (size_t)8192 * 1536, acc);
    upsample_add_kernel<<<16384, 256>>>(ahi, acc, Phi, Plo);

    gemm_mma<<<dim3(4, 256), 128, GEMM_SMEM>>>(Phi, Plo, Wph, Wpl, bproj,
                                               out, 512, 0,
                                               nullptr, nullptr, nullptr,
                                               nullptr, nullptr, nullptr);
}

// round 9
// speedup vs baseline: 1.3182x; 1.3182x over previous
#include <cuda_runtime.h>
#include <cuda_fp16.h>
#include <math.h>
#include <stdint.h>

typedef __half h16;

// ---------------------------------------------------------------------------
// HiLoAttention: B=8, N=4096 (64x64), C=512, heads=8, hd=64, window=2
// fp16x2 compensated arithmetic: activations split (Ah+Al), weights rounded.
//   prep -> fp16 hi/lo rows [40960,512]
//   gemm_mma mode1 -> hi rows: Qh/Ql (split,scaled) + Kh/Vh (rounded); lo: qcat
//   hi_attn_mma (fp16 HMMA flash), lo_attn, upsample+add -> fp16 hi/lo
//   gemm_mma mode0 + bias -> out
// ---------------------------------------------------------------------------

__device__ h16   g_Ahi[40960ull * 512];
__device__ h16   g_Alo[40960ull * 512];
__device__ h16   g_Wqh[1536 * 512];
__device__ h16   g_Wph[512 * 512];
__device__ float g_qcat[40960ull * 1536];
__device__ float g_ahi[8 * 1024 * 512];
__device__ float g_acc[8 * 4096 * 512];
__device__ h16   g_Phi[32768ull * 512];
__device__ h16   g_Plo[32768ull * 512];
__device__ h16   g_Qh[8 * 8 * 1024 * 64];
__device__ h16   g_Ql[8 * 8 * 1024 * 64];
__device__ h16   g_Kh[8 * 8 * 1024 * 64];
__device__ h16   g_Vh[8 * 8 * 1024 * 64];

// ------------------------------ helpers -------------------------------------
__device__ __forceinline__ uint32_t smem_u32(const void* p) {
    uint32_t a;
    asm("{ .reg .u64 t; cvta.to.shared.u64 t, %1; cvt.u32.u64 %0, t; }"
        : "=r"(a) : "l"(p));
    return a;
}
__device__ __forceinline__ void cp16(uint32_t dst, const void* src) {
    asm volatile("cp.async.cg.shared.global [%0], [%1], 16;"
                 :: "r"(dst), "l"(src) : "memory");
}
__device__ __forceinline__ uint32_t sw128(uint32_t off) {
    return off ^ ((off >> 3) & 0x70);
}
__device__ __forceinline__ void pack_split_h(float p0, float p1,
                                             uint32_t* hi, uint32_t* lo) {
    __half2 h2 = __floats2half2_rn(p0, p1);
    float2 f = __half22float2(h2);
    __half2 l2 = __floats2half2_rn(p0 - f.x, p1 - f.y);
    *hi = *(uint32_t*)&h2;
    *lo = *(uint32_t*)&l2;
}
__device__ __forceinline__ uint32_t pack_round_h(float p0, float p1) {
    __half2 h2 = __floats2half2_rn(p0, p1);
    return *(uint32_t*)&h2;
}
__device__ __forceinline__ void split4_store(float4 v, h16* H, h16* L,
                                             size_t off) {
    uint32_t h01, l01, h23, l23;
    pack_split_h(v.x, v.y, &h01, &l01);
    pack_split_h(v.z, v.w, &h23, &l23);
    *(uint2*)(H + off) = make_uint2(h01, h23);
    *(uint2*)(L + off) = make_uint2(l01, l23);
}

#define LDSM4(r, addr)                                                        \
    asm volatile("ldmatrix.sync.aligned.m8n8.x4.shared.b16 {%0,%1,%2,%3}, [%4];" \
                 : "=r"((r)[0]), "=r"((r)[1]), "=r"((r)[2]), "=r"((r)[3])     \
                 : "r"(addr))

#define LDSM4T(r, addr)                                                       \
    asm volatile("ldmatrix.sync.aligned.m8n8.x4.trans.shared.b16 {%0,%1,%2,%3}, [%4];" \
                 : "=r"((r)[0]), "=r"((r)[1]), "=r"((r)[2]), "=r"((r)[3])     \
                 : "r"(addr))

#define MMA16816(c, a, b0, b1)                                                \
    asm volatile("mma.sync.aligned.m16n8k16.row.col.f32.f16.f16.f32 "         \
                 "{%0,%1,%2,%3},{%4,%5,%6,%7},{%8,%9},{%0,%1,%2,%3};"         \
                 : "+f"((c)[0]), "+f"((c)[1]), "+f"((c)[2]), "+f"((c)[3])     \
                 : "r"((a)[0]), "r"((a)[1]), "r"((a)[2]), "r"((a)[3]),        \
                   "r"(b0), "r"(b1))

// ------------------- fused pool + window (block per (b,w)) -------------------
__global__ __launch_bounds__(128) void prep_kernel(const float* __restrict__ x,
                                                   h16* __restrict__ Ahi,
                                                   h16* __restrict__ Alo) {
    __shared__ float xs[4][512];
    const int w = blockIdx.x & 1023, b = blockIdx.x >> 10;
    const int hh = w >> 5, wh = w & 31;
    const int tid = threadIdx.x;
    const int tok0 = (hh * 2) * 64 + wh * 2;
    const float* xb = x + ((size_t)b * 4096) * 512;
    const int toks[4] = {tok0, tok0 + 1, tok0 + 64, tok0 + 65};
#pragma unroll
    for (int s = 0; s < 4; ++s) {
        const float4* src = (const float4*)(xb + (size_t)toks[s] * 512);
        *(float4*)&xs[s][tid * 4] = src[tid];
    }
    __syncthreads();
    {
        int c = tid * 4;
        float4 a = *(float4*)&xs[0][c];
        float4 b2 = *(float4*)&xs[1][c];
        float4 c2 = *(float4*)&xs[2][c];
        float4 d2 = *(float4*)&xs[3][c];
        float4 v = {0.25f * (a.x + b2.x + c2.x + d2.x),
                    0.25f * (a.y + b2.y + c2.y + d2.y),
                    0.25f * (a.z + b2.z + c2.z + d2.z),
                    0.25f * (a.w + b2.w + c2.w + d2.w)};
        split4_store(v, Ahi, Alo, (size_t)(b * 1024 + w) * 512 + c);
    }
#pragma unroll
    for (int t = 0; t < 4; ++t) {
        int u = tid;
        float4 v = {xs[0][t * 128 + u], xs[1][t * 128 + u],
                    xs[2][t * 128 + u], xs[3][t * 128 + u]};
        size_t wrow = (size_t)(8192 + (b * 1024 + w) * 4 + t) * 512;
        split4_store(v, Ahi, Alo, wrow + u * 4);
    }
}

// ------------------- weight round (fp16, vectorized) -------------------------
__global__ __launch_bounds__(256) void round_kernel(const float* __restrict__ src,
                                                    h16* __restrict__ hi, int n4) {
    int g = blockIdx.x * 256 + threadIdx.x;
    if (g >= n4) return;
    float4 v = ((const float4*)src)[g];
    uint2 o = make_uint2(pack_round_h(v.x, v.y), pack_round_h(v.z, v.w));
    *(uint2*)(hi + (size_t)g * 4) = o;
}

// -------------- fp16x2 HMMA GEMM (K=512), 4 warps, 64x64 warp tile -----------
// C = (Ah + Al) * Bh^T; 3 matrices per stage (Ah, Al, Bh), 2 products.
#define GEMM_SMEM (2 * 24576 + 1024)

__global__ __launch_bounds__(128) void gemm_mma(
    const h16* __restrict__ Ah, const h16* __restrict__ Al,
    const h16* __restrict__ Bh,
    const float* __restrict__ bias, float* __restrict__ C, int N, int mode,
    h16* __restrict__ Qh, h16* __restrict__ Ql,
    h16* __restrict__ Kh, h16* __restrict__ Vh) {
    extern __shared__ char dynsm[];
    const int tid = threadIdx.x;
    const int wid = tid >> 5, lane = tid & 31;
    const int wm = wid & 1, wn = wid >> 1;
    const size_t bm = (size_t)blockIdx.y * 128;
    const size_t bn = (size_t)blockIdx.x * 128;
    const uint32_t sb = (smem_u32(dynsm) + 1023) & ~1023u;

    const char* srcs[3] = {(const char*)(Ah + bm * 512),
                           (const char*)(Al + bm * 512),
                           (const char*)(Bh + bn * 512)};

    auto load_chunk = [&](int kc, int s) {
        const uint32_t base = sb + s * 24576;
#pragma unroll
        for (int mat = 0; mat < 3; ++mat) {
#pragma unroll
            for (int j = 0; j < 4; ++j) {
                uint32_t u = tid + j * 128;
                uint32_t r = u >> 2, c16 = u & 3;
                cp16(base + mat * 8192 + sw128(u * 16),
                     srcs[mat] + (size_t)r * 1024 + kc * 64 + c16 * 16);
            }
        }
        asm volatile("cp.async.commit_group;" ::: "memory");
    };

    float c[4][8][4];
#pragma unroll
    for (int i = 0; i < 4; ++i)
#pragma unroll
        for (int j = 0; j < 8; ++j)
#pragma unroll
            for (int q = 0; q < 4; ++q) c[i][j][q] = 0.f;

    const int sub = lane >> 3;
    const int rowl = ((sub & 1) << 3) + (lane & 7);
    const int csel = sub >> 1;

    load_chunk(0, 0);
    load_chunk(1, 1);

#pragma unroll 1
    for (int kc = 0; kc < 16; ++kc) {
        const int s = kc & 1;
        if (kc < 15) asm volatile("cp.async.wait_group 1;" ::: "memory");
        else         asm volatile("cp.async.wait_group 0;" ::: "memory");
        __syncthreads();
        const uint32_t st = sb + s * 24576;

#pragma unroll
        for (int kk = 0; kk < 2; ++kk) {
            uint32_t bh4[2][4];
            {
                uint32_t off = (uint32_t)(wn * 64 + rowl) * 64 +
                               (uint32_t)(kk * 2 + csel) * 16;
                LDSM4(bh4[0], st + 16384 + sw128(off));
            }
            uint32_t ah[4][4], al[4][4];
#pragma unroll
            for (int mt = 0; mt < 4; ++mt) {
                uint32_t off = (uint32_t)(wm * 64 + mt * 16 + rowl) * 64 +
                               (uint32_t)(kk * 2 + csel) * 16;
                LDSM4(ah[mt], st + sw128(off));
                LDSM4(al[mt], st + 8192 + sw128(off));
            }
#pragma unroll
            for (int nb = 0; nb < 4; ++nb) {
                const int p = nb & 1;
                if (nb < 3) {
                    uint32_t off = (uint32_t)(wn * 64 + (nb + 1) * 16 + rowl) * 64 +
                                   (uint32_t)(kk * 2 + csel) * 16;
                    LDSM4(bh4[p ^ 1], st + 16384 + sw128(off));
                }
#pragma unroll
                for (int mt = 0; mt < 4; ++mt) {
                    MMA16816(c[mt][nb * 2], ah[mt], bh4[p][0], bh4[p][2]);
                    MMA16816(c[mt][nb * 2 + 1], ah[mt], bh4[p][1], bh4[p][3]);
                }
#pragma unroll
                for (int mt = 0; mt < 4; ++mt) {
                    MMA16816(c[mt][nb * 2], al[mt], bh4[p][0], bh4[p][2]);
                    MMA16816(c[mt][nb * 2 + 1], al[mt], bh4[p][1], bh4[p][3]);
                }
            }
        }
        __syncthreads();
        if (kc + 2 < 16) load_chunk(kc + 2, s);
    }

    const int r0 = lane >> 2;
    const int c0 = (lane & 3) * 2;
    if (mode == 1 && bm < 8192) {
#pragma unroll
        for (int mt = 0; mt < 4; ++mt)
#pragma unroll
            for (int n8 = 0; n8 < 8; ++n8) {
                int col = (int)bn + wn * 64 + n8 * 8 + c0;
                int which = col >> 9, jj = col & 511;
                int h = jj >> 6, d = jj & 63;
#pragma unroll
                for (int half = 0; half < 2; ++half) {
                    int row = (int)bm + wm * 64 + mt * 16 + r0 + half * 8;
                    int b = row >> 10, tok = row & 1023;
                    size_t dst = ((size_t)((b * 8 + h) * 1024 + tok)) * 64 + d;
                    float v0 = c[mt][n8][half * 2], v1 = c[mt][n8][half * 2 + 1];
                    if (which == 0) {
                        uint32_t hu, lu;
                        pack_split_h(v0 * 0.125f, v1 * 0.125f, &hu, &lu);
                        *(uint32_t*)(Qh + dst) = hu;
                        *(uint32_t*)(Ql + dst) = lu;
                    } else if (which == 1) {
                        *(uint32_t*)(Kh + dst) = pack_round_h(v0, v1);
                    } else {
                        *(uint32_t*)(Vh + dst) = pack_round_h(v0, v1);
                    }
                }
            }
    } else {
#pragma unroll
        for (int mt = 0; mt < 4; ++mt)
#pragma unroll
            for (int n8 = 0; n8 < 8; ++n8) {
                size_t row = bm + wm * 64 + mt * 16 + r0;
                size_t col = bn + wn * 64 + n8 * 8 + c0;
                float bx = 0.f, by = 0.f;
                if (bias) { bx = bias[col]; by = bias[col + 1]; }
                float2 v0 = {c[mt][n8][0] + bx, c[mt][n8][1] + by};
                float2 v1 = {c[mt][n8][2] + bx, c[mt][n8][3] + by};
                *(float2*)(C + row * (size_t)N + col) = v0;
                *(float2*)(C + (row + 8) * (size_t)N + col) = v1;
            }
    }
}

// ------------------- fp16 HMMA flash attention (hi branch) -------------------
// KV stage: Kh + Vh = 16KB; Q split fp16x2 in fragments; P split in registers.
#define ATT_SMEM (2 * 16384 + 1024)

__global__ __launch_bounds__(128) void hi_attn_mma(
    const h16* __restrict__ Qh, const h16* __restrict__ Ql,
    const h16* __restrict__ Kh, const h16* __restrict__ Vh,
    float* __restrict__ out) {
    extern __shared__ char dynsm[];
    const int tid = threadIdx.x;
    const int wid = tid >> 5, lane = tid & 31;
    const int qt = blockIdx.x, h = blockIdx.y, b = blockIdx.z;
    const uint32_t sb = (smem_u32(dynsm) + 1023) & ~1023u;
    const size_t bh = (size_t)(b * 8 + h) * 65536;

    const int sub = lane >> 3;
    const int rowl = ((sub & 1) << 3) + (lane & 7);
    const int csel = sub >> 1;

    {
        const char* qh_src = (const char*)(Qh + bh + (size_t)qt * 64 * 64);
        const char* ql_src = (const char*)(Ql + bh + (size_t)qt * 64 * 64);
#pragma unroll
        for (int u = tid; u < 512; u += 128) {
            cp16(sb + sw128(u * 16), qh_src + u * 16);
            cp16(sb + 8192 + sw128(u * 16), ql_src + u * 16);
        }
        asm volatile("cp.async.commit_group;" ::: "memory");
        asm volatile("cp.async.wait_group 0;" ::: "memory");
        __syncthreads();
    }
    uint32_t qh[4][4], ql[4][4];
#pragma unroll
    for (int kf = 0; kf < 4; ++kf) {
        uint32_t off = (uint32_t)(wid * 16 + rowl) * 128 + kf * 32 + csel * 16;
        LDSM4(qh[kf], sb + sw128(off));
        LDSM4(ql[kf], sb + 8192 + sw128(off));
    }
    __syncthreads();

    const char* kh_src = (const char*)(Kh + bh);
    const char* vh_src = (const char*)(Vh + bh);

    auto load_kv = [&](int kt, int s) {
        const uint32_t base = sb + s * 16384;
        const size_t go = (size_t)kt * 8192;
#pragma unroll
        for (int u = tid; u < 512; u += 128) {
            uint32_t sw = sw128(u * 16);
            cp16(base + sw, kh_src + go + u * 16);
            cp16(base + 8192 + sw, vh_src + go + u * 16);
        }
        asm volatile("cp.async.commit_group;" ::: "memory");
    };

    load_kv(0, 0);
    load_kv(1, 1);

    float o[8][4];
#pragma unroll
    for (int i = 0; i < 8; ++i)
#pragma unroll
        for (int j = 0; j < 4; ++j) o[i][j] = 0.f;
    float m0 = -1e30f, m1 = -1e30f, l0 = 0.f, l1 = 0.f;

#pragma unroll 1
    for (int kt = 0; kt < 16; ++kt) {
        const int s = kt & 1;
        if (kt < 15) asm volatile("cp.async.wait_group 1;" ::: "memory");
        else         asm volatile("cp.async.wait_group 0;" ::: "memory");
        __syncthreads();
        const uint32_t base = sb + s * 16384;

        float sfr[8][4];
#pragma unroll
        for (int i = 0; i < 8; ++i)
#pragma unroll
            for (int j = 0; j < 4; ++j) sfr[i][j] = 0.f;

#pragma unroll
        for (int kf = 0; kf < 4; ++kf) {
            uint32_t kbh[4][4];
#pragma unroll
            for (int nb = 0; nb < 4; ++nb) {
                uint32_t off = (uint32_t)(nb * 16 + rowl) * 128 + kf * 32 + csel * 16;
                LDSM4(kbh[nb], base + sw128(off));
            }
#pragma unroll
            for (int nb = 0; nb < 4; ++nb) {
                MMA16816(sfr[nb * 2], qh[kf], kbh[nb][0], kbh[nb][2]);
                MMA16816(sfr[nb * 2 + 1], qh[kf], kbh[nb][1], kbh[nb][3]);
            }
#pragma unroll
            for (int nb = 0; nb < 4; ++nb) {
                MMA16816(sfr[nb * 2], ql[kf], kbh[nb][0], kbh[nb][2]);
                MMA16816(sfr[nb * 2 + 1], ql[kf], kbh[nb][1], kbh[nb][3]);
            }
        }

        float mx0 = -1e30f, mx1 = -1e30f;
#pragma unroll
        for (int n8 = 0; n8 < 8; ++n8) {
            mx0 = fmaxf(mx0, fmaxf(sfr[n8][0], sfr[n8][1]));
            mx1 = fmaxf(mx1, fmaxf(sfr[n8][2], sfr[n8][3]));
        }
        mx0 = fmaxf(mx0, __shfl_xor_sync(0xffffffffu, mx0, 1));
        mx0 = fmaxf(mx0, __shfl_xor_sync(0xffffffffu, mx0, 2));
        mx1 = fmaxf(mx1, __shfl_xor_sync(0xffffffffu, mx1, 1));
        mx1 = fmaxf(mx1, __shfl_xor_sync(0xffffffffu, mx1, 2));
        float m0n = fmaxf(m0, mx0), m1n = fmaxf(m1, mx1);
        float c0 = __expf(m0 - m0n), c1 = __expf(m1 - m1n);
        m0 = m0n; m1 = m1n;
        float s0 = 0.f, s1 = 0.f;
#pragma unroll
        for (int n8 = 0; n8 < 8; ++n8) {
            sfr[n8][0] = __expf(sfr[n8][0] - m0n);
            sfr[n8][1] = __expf(sfr[n8][1] - m0n);
            sfr[n8][2] = __expf(sfr[n8][2] - m1n);
            sfr[n8][3] = __expf(sfr[n8][3] - m1n);
            s0 += sfr[n8][0] + sfr[n8][1];
            s1 += sfr[n8][2] + sfr[n8][3];
        }
        s0 += __shfl_xor_sync(0xffffffffu, s0, 1);
        s0 += __shfl_xor_sync(0xffffffffu, s0, 2);
        s1 += __shfl_xor_sync(0xffffffffu, s1, 1);
        s1 += __shfl_xor_sync(0xffffffffu, s1, 2);
        l0 = l0 * c0 + s0;
        l1 = l1 * c1 + s1;
#pragma unroll
        for (int n8 = 0; n8 < 8; ++n8) {
            o[n8][0] *= c0; o[n8][1] *= c0;
            o[n8][2] *= c1; o[n8][3] *= c1;
        }

#pragma unroll
        for (int kf = 0; kf < 4; ++kf) {
            uint32_t ah4[4], al4[4];
            pack_split_h(sfr[2 * kf][0], sfr[2 * kf][1], &ah4[0], &al4[0]);
            pack_split_h(sfr[2 * kf][2], sfr[2 * kf][3], &ah4[1], &al4[1]);
            pack_split_h(sfr[2 * kf + 1][0], sfr[2 * kf + 1][1], &ah4[2], &al4[2]);
            pack_split_h(sfr[2 * kf + 1][2], sfr[2 * kf + 1][3], &ah4[3], &al4[3]);
            uint32_t vbh[4][4];
#pragma unroll
            for (int dd = 0; dd < 4; ++dd) {
                uint32_t off = (uint32_t)(kf * 16 + rowl) * 128 + dd * 32 + csel * 16;
                LDSM4T(vbh[dd], base + 8192 + sw128(off));
            }
#pragma unroll
            for (int dd = 0; dd < 4; ++dd) {
                MMA16816(o[dd * 2], ah4, vbh[dd][0], vbh[dd][1]);
                MMA16816(o[dd * 2 + 1], ah4, vbh[dd][2], vbh[dd][3]);
            }
#pragma unroll
            for (int dd = 0; dd < 4; ++dd) {
                MMA16816(o[dd * 2], al4, vbh[dd][0], vbh[dd][1]);
                MMA16816(o[dd * 2 + 1], al4, vbh[dd][2], vbh[dd][3]);
            }
        }
        __syncthreads();
        if (kt + 2 < 16) load_kv(kt + 2, s);
    }

    float inv0 = 1.0f / l0, inv1 = 1.0f / l1;
    int r0 = lane >> 2, cc = (lane & 3) * 2;
    size_t row = (size_t)(b * 1024 + qt * 64 + wid * 16 + r0);
#pragma unroll
    for (int n8 = 0; n8 < 8; ++n8) {
        size_t col = h * 64 + n8 * 8 + cc;
        float2 v0 = {o[n8][0] * inv0, o[n8][1] * inv0};
        float2 v1 = {o[n8][2] * inv1, o[n8][3] * inv1};
        *(float2*)(out + row * 512 + col) = v0;
        *(float2*)(out + (row + 8) * 512 + col) = v1;
    }
}

// ----------------------------- lo attention ---------------------------------
__global__ __launch_bounds__(256) void lo_attn_kernel(const float* __restrict__ qkv,
                                                      float* __restrict__ acc) {
    int gw = (blockIdx.x * 256 + threadIdx.x) >> 5;
    int lane = threadIdx.x & 31;
    int h = gw & 7;
    int w = (gw >> 3) & 1023;
    int b = gw >> 13;
    const float* base = qkv + (size_t)(b * 4096 + w * 4) * 1536 + h * 64 + lane;
    float q[4][2], k[4][2], v[4][2];
#pragma unroll
    for (int t = 0; t < 4; ++t) {
        const float* r = base + t * 1536;
        q[t][0] = r[0];    q[t][1] = r[32];
        k[t][0] = r[512];  k[t][1] = r[544];
        v[t][0] = r[1024]; v[t][1] = r[1056];
    }
    float lg[4][4];
#pragma unroll
    for (int t = 0; t < 4; ++t)
#pragma unroll
        for (int s2 = 0; s2 < 4; ++s2)
            lg[t][s2] = q[t][0] * k[s2][0] + q[t][1] * k[s2][1];
#pragma unroll
    for (int off = 16; off; off >>= 1)
#pragma unroll
        for (int t = 0; t < 4; ++t)
#pragma unroll
            for (int s2 = 0; s2 < 4; ++s2)
                lg[t][s2] += __shfl_xor_sync(0xffffffffu, lg[t][s2], off);

    int hh = w >> 5, wh = w & 31;
#pragma unroll
    for (int t = 0; t < 4; ++t) {
        float L0 = lg[t][0] * 0.125f, L1 = lg[t][1] * 0.125f;
        float L2 = lg[t][2] * 0.125f, L3 = lg[t][3] * 0.125f;
        float m = fmaxf(fmaxf(L0, L1), fmaxf(L2, L3));
        float p0 = __expf(L0 - m), p1 = __expf(L1 - m);
        float p2 = __expf(L2 - m), p3 = __expf(L3 - m);
        float inv = 1.0f / (p0 + p1 + p2 + p3);
        float o0 = (p0 * v[0][0] + p1 * v[1][0] + p2 * v[2][0] + p3 * v[3][0]) * inv;
        float o1 = (p0 * v[0][1] + p1 * v[1][1] + p2 * v[2][1] + p3 * v[3][1]) * inv;
        int tok = (hh * 2 + (t >> 1)) * 64 + wh * 2 + (t & 1);
        float* op = acc + (size_t)(b * 4096 + tok) * 512 + h * 64 + lane;
        op[0] = o0;
        op[32] = o1;
    }
}

// --------- bilinear upsample + add -> fp16 hi/lo split (vectorized) ----------
__global__ __launch_bounds__(256) void upsample_add_kernel(const float* __restrict__ hi,
                                                           const float* __restrict__ acc,
                                                           h16* __restrict__ ph,
                                                           h16* __restrict__ pl) {
    int g = blockIdx.x * 256 + threadIdx.x;
    if (g >= 8 * 4096 * 128) return;
    int c = (g & 127) * 4;
    int tok = (g >> 7) & 4095;
    int b = g >> 19;
    int y = tok >> 6, x = tok & 63;
    float fy = 0.5f * y - 0.25f;
    float fx = 0.5f * x - 0.25f;
    int y0 = (int)floorf(fy);
    int x0 = (int)floorf(fx);
    float wy = fy - (float)y0;
    float wx = fx - (float)x0;
    int y0c = max(y0, 0), y1c = min(y0 + 1, 31);
    int x0c = max(x0, 0), x1c = min(x0 + 1, 31);
    const float* hp = hi + (size_t)b * 1024 * 512 + c;
    float4 v00 = *(const float4*)(hp + (size_t)(y0c * 32 + x0c) * 512);
    float4 v01 = *(const float4*)(hp + (size_t)(y0c * 32 + x1c) * 512);
    float4 v10 = *(const float4*)(hp + (size_t)(y1c * 32 + x0c) * 512);
    float4 v11 = *(const float4*)(hp + (size_t)(y1c * 32 + x1c) * 512);
    float w00 = (1.f - wy) * (1.f - wx), w01 = (1.f - wy) * wx;
    float w10 = wy * (1.f - wx), w11 = wy * wx;
    size_t idx = ((size_t)(b * 4096 + tok)) * 512 + c;
    float4 a = *(const float4*)(acc + idx);
    float4 r;
    r.x = a.x + w00 * v00.x + w01 * v01.x + w10 * v10.x + w11 * v11.x;
    r.y = a.y + w00 * v00.y + w01 * v01.y + w10 * v10.y + w11 * v11.y;
    r.z = a.z + w00 * v00.z + w01 * v01.z + w10 * v10.z + w11 * v11.z;
    r.w = a.w + w00 * v00.w + w01 * v01.w + w10 * v10.w + w11 * v11.w;
    split4_store(r, ph, pl, idx);
}

// --------------------------------- launch -----------------------------------
extern "C" void kernel_launch(void* const* d_in, const int* in_sizes, int n_in,
                              void* d_out, int out_size) {
    const float* x     = (const float*)d_in[0];
    const float* Wqkv  = (const float*)d_in[1];
    const float* Wproj = (const float*)d_in[2];
    const float* bproj = (const float*)d_in[3];
    float* out = (float*)d_out;

    h16 *Ahi, *Alo, *Wqh, *Wph, *Phi, *Plo, *Qh, *Ql, *Kh, *Vh;
    float *qcat, *ahi, *acc;
    cudaGetSymbolAddress((void**)&Ahi, g_Ahi);
    cudaGetSymbolAddress((void**)&Alo, g_Alo);
    cudaGetSymbolAddress((void**)&Wqh, g_Wqh);
    cudaGetSymbolAddress((void**)&Wph, g_Wph);
    cudaGetSymbolAddress((void**)&Phi, g_Phi);
    cudaGetSymbolAddress((void**)&Plo, g_Plo);
    cudaGetSymbolAddress((void**)&qcat, g_qcat);
    cudaGetSymbolAddress((void**)&ahi, g_ahi);
    cudaGetSymbolAddress((void**)&acc, g_acc);
    cudaGetSymbolAddress((void**)&Qh, g_Qh);
    cudaGetSymbolAddress((void**)&Ql, g_Ql);
    cudaGetSymbolAddress((void**)&Kh, g_Kh);
    cudaGetSymbolAddress((void**)&Vh, g_Vh);

    cudaFuncSetAttribute((const void*)gemm_mma,
                         cudaFuncAttributeMaxDynamicSharedMemorySize, GEMM_SMEM);
    cudaFuncSetAttribute((const void*)hi_attn_mma,
                         cudaFuncAttributeMaxDynamicSharedMemorySize, ATT_SMEM);

    prep_kernel<<<8192, 128>>>(x, Ahi, Alo);
    round_kernel<<<768, 256>>>(Wqkv, Wqh, 1536 * 512 / 4);
    round_kernel<<<256, 256>>>(Wproj, Wph, 512 * 512 / 4);

    gemm_mma<<<dim3(12, 320), 128, GEMM_SMEM>>>(Ahi, Alo, Wqh, nullptr,
                                                qcat, 1536, 1, Qh, Ql, Kh, Vh);

    hi_attn_mma<<<dim3(16, 8, 8), 128, ATT_SMEM>>>(Qh, Ql, Kh, Vh, ahi);
    lo_attn_kernel<<<8192, 256>>>(qcat + (size_t)8192 * 1536, acc);
    upsample_add_kernel<<<16384, 256>>>(ahi, acc, Phi, Plo);

    gemm_mma<<<dim3(4, 256), 128, GEMM_SMEM>>>(Phi, Plo, Wph, bproj,
                                               out, 512, 0,
                                               nullptr, nullptr, nullptr, nullptr);
}

// round 10
// speedup vs baseline: 1.3289x; 1.0081x over previous
#include <cuda_runtime.h>
#include <cuda_fp16.h>
#include <math.h>
#include <stdint.h>

typedef __half h16;

// ---------------------------------------------------------------------------
// HiLoAttention: B=8, N=4096 (64x64), C=512, heads=8, hd=64, window=2
// fp16x2 compensated arithmetic: activations split (Ah+Al), weights rounded.
//   prep -> fp16 hi/lo rows [40960,512]
//   gemm_mma mode1 -> hi rows: Qh/Ql (split,scaled) + Kh/Vh (rounded); lo: qcat
//   hi_attn_mma (fp16 HMMA flash), lo_attn, upsample+add -> fp16 hi/lo
//   gemm_mma mode0 + bias -> out
//   Round 10: GEMM 256 thr / 8 warps / 64x32 warp tiles -> 4 warps/SMSP
// ---------------------------------------------------------------------------

__device__ h16   g_Ahi[40960ull * 512];
__device__ h16   g_Alo[40960ull * 512];
__device__ h16   g_Wqh[1536 * 512];
__device__ h16   g_Wph[512 * 512];
__device__ float g_qcat[40960ull * 1536];
__device__ float g_ahi[8 * 1024 * 512];
__device__ float g_acc[8 * 4096 * 512];
__device__ h16   g_Phi[32768ull * 512];
__device__ h16   g_Plo[32768ull * 512];
__device__ h16   g_Qh[8 * 8 * 1024 * 64];
__device__ h16   g_Ql[8 * 8 * 1024 * 64];
__device__ h16   g_Kh[8 * 8 * 1024 * 64];
__device__ h16   g_Vh[8 * 8 * 1024 * 64];

// ------------------------------ helpers -------------------------------------
__device__ __forceinline__ uint32_t smem_u32(const void* p) {
    uint32_t a;
    asm("{ .reg .u64 t; cvta.to.shared.u64 t, %1; cvt.u32.u64 %0, t; }"
        : "=r"(a) : "l"(p));
    return a;
}
__device__ __forceinline__ void cp16(uint32_t dst, const void* src) {
    asm volatile("cp.async.cg.shared.global [%0], [%1], 16;"
                 :: "r"(dst), "l"(src) : "memory");
}
__device__ __forceinline__ uint32_t sw128(uint32_t off) {
    return off ^ ((off >> 3) & 0x70);
}
__device__ __forceinline__ void pack_split_h(float p0, float p1,
                                             uint32_t* hi, uint32_t* lo) {
    __half2 h2 = __floats2half2_rn(p0, p1);
    float2 f = __half22float2(h2);
    __half2 l2 = __floats2half2_rn(p0 - f.x, p1 - f.y);
    *hi = *(uint32_t*)&h2;
    *lo = *(uint32_t*)&l2;
}
__device__ __forceinline__ uint32_t pack_round_h(float p0, float p1) {
    __half2 h2 = __floats2half2_rn(p0, p1);
    return *(uint32_t*)&h2;
}
__device__ __forceinline__ void split4_store(float4 v, h16* H, h16* L,
                                             size_t off) {
    uint32_t h01, l01, h23, l23;
    pack_split_h(v.x, v.y, &h01, &l01);
    pack_split_h(v.z, v.w, &h23, &l23);
    *(uint2*)(H + off) = make_uint2(h01, h23);
    *(uint2*)(L + off) = make_uint2(l01, l23);
}

#define LDSM4(r, addr)                                                        \
    asm volatile("ldmatrix.sync.aligned.m8n8.x4.shared.b16 {%0,%1,%2,%3}, [%4];" \
                 : "=r"((r)[0]), "=r"((r)[1]), "=r"((r)[2]), "=r"((r)[3])     \
                 : "r"(addr))

#define LDSM4T(r, addr)                                                       \
    asm volatile("ldmatrix.sync.aligned.m8n8.x4.trans.shared.b16 {%0,%1,%2,%3}, [%4];" \
                 : "=r"((r)[0]), "=r"((r)[1]), "=r"((r)[2]), "=r"((r)[3])     \
                 : "r"(addr))

#define MMA16816(c, a, b0, b1)                                                \
    asm volatile("mma.sync.aligned.m16n8k16.row.col.f32.f16.f16.f32 "         \
                 "{%0,%1,%2,%3},{%4,%5,%6,%7},{%8,%9},{%0,%1,%2,%3};"         \
                 : "+f"((c)[0]), "+f"((c)[1]), "+f"((c)[2]), "+f"((c)[3])     \
                 : "r"((a)[0]), "r"((a)[1]), "r"((a)[2]), "r"((a)[3]),        \
                   "r"(b0), "r"(b1))

// ------------------- fused pool + window (block per (b,w)) -------------------
__global__ __launch_bounds__(128) void prep_kernel(const float* __restrict__ x,
                                                   h16* __restrict__ Ahi,
                                                   h16* __restrict__ Alo) {
    __shared__ float xs[4][512];
    const int w = blockIdx.x & 1023, b = blockIdx.x >> 10;
    const int hh = w >> 5, wh = w & 31;
    const int tid = threadIdx.x;
    const int tok0 = (hh * 2) * 64 + wh * 2;
    const float* xb = x + ((size_t)b * 4096) * 512;
    const int toks[4] = {tok0, tok0 + 1, tok0 + 64, tok0 + 65};
#pragma unroll
    for (int s = 0; s < 4; ++s) {
        const float4* src = (const float4*)(xb + (size_t)toks[s] * 512);
        *(float4*)&xs[s][tid * 4] = src[tid];
    }
    __syncthreads();
    {
        int c = tid * 4;
        float4 a = *(float4*)&xs[0][c];
        float4 b2 = *(float4*)&xs[1][c];
        float4 c2 = *(float4*)&xs[2][c];
        float4 d2 = *(float4*)&xs[3][c];
        float4 v = {0.25f * (a.x + b2.x + c2.x + d2.x),
                    0.25f * (a.y + b2.y + c2.y + d2.y),
                    0.25f * (a.z + b2.z + c2.z + d2.z),
                    0.25f * (a.w + b2.w + c2.w + d2.w)};
        split4_store(v, Ahi, Alo, (size_t)(b * 1024 + w) * 512 + c);
    }
#pragma unroll
    for (int t = 0; t < 4; ++t) {
        int u = tid;
        float4 v = {xs[0][t * 128 + u], xs[1][t * 128 + u],
                    xs[2][t * 128 + u], xs[3][t * 128 + u]};
        size_t wrow = (size_t)(8192 + (b * 1024 + w) * 4 + t) * 512;
        split4_store(v, Ahi, Alo, wrow + u * 4);
    }
}

// ------------------- weight round (fp16, vectorized) -------------------------
__global__ __launch_bounds__(256) void round_kernel(const float* __restrict__ src,
                                                    h16* __restrict__ hi, int n4) {
    int g = blockIdx.x * 256 + threadIdx.x;
    if (g >= n4) return;
    float4 v = ((const float4*)src)[g];
    uint2 o = make_uint2(pack_round_h(v.x, v.y), pack_round_h(v.z, v.w));
    *(uint2*)(hi + (size_t)g * 4) = o;
}

// ---------- fp16x2 HMMA GEMM (K=512), 8 warps (2x4), 64x32 warp tile ---------
// C = (Ah + Al) * Bh^T; 3 matrices per stage (Ah, Al, Bh), 2 products.
#define GEMM_SMEM (2 * 24576 + 1024)

__global__ __launch_bounds__(256, 2) void gemm_mma(
    const h16* __restrict__ Ah, const h16* __restrict__ Al,
    const h16* __restrict__ Bh,
    const float* __restrict__ bias, float* __restrict__ C, int N, int mode,
    h16* __restrict__ Qh, h16* __restrict__ Ql,
    h16* __restrict__ Kh, h16* __restrict__ Vh) {
    extern __shared__ char dynsm[];
    const int tid = threadIdx.x;
    const int wid = tid >> 5, lane = tid & 31;
    const int wm = wid & 1, wn = wid >> 1;              // 2 x 4 warp grid
    const size_t bm = (size_t)blockIdx.y * 128;
    const size_t bn = (size_t)blockIdx.x * 128;
    const uint32_t sb = (smem_u32(dynsm) + 1023) & ~1023u;

    const char* srcs[3] = {(const char*)(Ah + bm * 512),
                           (const char*)(Al + bm * 512),
                           (const char*)(Bh + bn * 512)};

    auto load_chunk = [&](int kc, int s) {
        const uint32_t base = sb + s * 24576;
#pragma unroll
        for (int mat = 0; mat < 3; ++mat) {
#pragma unroll
            for (int j = 0; j < 2; ++j) {
                uint32_t u = tid + j * 256;
                uint32_t r = u >> 2, c16 = u & 3;
                cp16(base + mat * 8192 + sw128(u * 16),
                     srcs[mat] + (size_t)r * 1024 + kc * 64 + c16 * 16);
            }
        }
        asm volatile("cp.async.commit_group;" ::: "memory");
    };

    // accumulators: 4 m16-tiles x 4 n8-tiles (64 regs)
    float c[4][4][4];
#pragma unroll
    for (int i = 0; i < 4; ++i)
#pragma unroll
        for (int j = 0; j < 4; ++j)
#pragma unroll
            for (int q = 0; q < 4; ++q) c[i][j][q] = 0.f;

    const int sub = lane >> 3;
    const int rowl = ((sub & 1) << 3) + (lane & 7);
    const int csel = sub >> 1;

    load_chunk(0, 0);
    load_chunk(1, 1);

#pragma unroll 1
    for (int kc = 0; kc < 16; ++kc) {
        const int s = kc & 1;
        if (kc < 15) asm volatile("cp.async.wait_group 1;" ::: "memory");
        else         asm volatile("cp.async.wait_group 0;" ::: "memory");
        __syncthreads();
        const uint32_t st = sb + s * 24576;

#pragma unroll
        for (int kk = 0; kk < 2; ++kk) {
            uint32_t bh4[2][4];
            {
                uint32_t off = (uint32_t)(wn * 32 + rowl) * 64 +
                               (uint32_t)(kk * 2 + csel) * 16;
                LDSM4(bh4[0], st + 16384 + sw128(off));
            }
            uint32_t ah[4][4], al[4][4];
#pragma unroll
            for (int mt = 0; mt < 4; ++mt) {
                uint32_t off = (uint32_t)(wm * 64 + mt * 16 + rowl) * 64 +
                               (uint32_t)(kk * 2 + csel) * 16;
                LDSM4(ah[mt], st + sw128(off));
                LDSM4(al[mt], st + 8192 + sw128(off));
            }
#pragma unroll
            for (int nb = 0; nb < 2; ++nb) {
                const int p = nb & 1;
                if (nb < 1) {
                    uint32_t off = (uint32_t)(wn * 32 + 16 + rowl) * 64 +
                                   (uint32_t)(kk * 2 + csel) * 16;
                    LDSM4(bh4[1], st + 16384 + sw128(off));
                }
#pragma unroll
                for (int mt = 0; mt < 4; ++mt) {
                    MMA16816(c[mt][nb * 2], ah[mt], bh4[p][0], bh4[p][2]);
                    MMA16816(c[mt][nb * 2 + 1], ah[mt], bh4[p][1], bh4[p][3]);
                }
#pragma unroll
                for (int mt = 0; mt < 4; ++mt) {
                    MMA16816(c[mt][nb * 2], al[mt], bh4[p][0], bh4[p][2]);
                    MMA16816(c[mt][nb * 2 + 1], al[mt], bh4[p][1], bh4[p][3]);
                }
            }
        }
        __syncthreads();
        if (kc + 2 < 16) load_chunk(kc + 2, s);
    }

    const int r0 = lane >> 2;
    const int c0 = (lane & 3) * 2;
    if (mode == 1 && bm < 8192) {
#pragma unroll
        for (int mt = 0; mt < 4; ++mt)
#pragma unroll
            for (int j = 0; j < 4; ++j) {
                int col = (int)bn + wn * 32 + j * 8 + c0;
                int which = col >> 9, jj = col & 511;
                int h = jj >> 6, d = jj & 63;
#pragma unroll
                for (int half = 0; half < 2; ++half) {
                    int row = (int)bm + wm * 64 + mt * 16 + r0 + half * 8;
                    int b = row >> 10, tok = row & 1023;
                    size_t dst = ((size_t)((b * 8 + h) * 1024 + tok)) * 64 + d;
                    float v0 = c[mt][j][half * 2], v1 = c[mt][j][half * 2 + 1];
                    if (which == 0) {
                        uint32_t hu, lu;
                        pack_split_h(v0 * 0.125f, v1 * 0.125f, &hu, &lu);
                        *(uint32_t*)(Qh + dst) = hu;
                        *(uint32_t*)(Ql + dst) = lu;
                    } else if (which == 1) {
                        *(uint32_t*)(Kh + dst) = pack_round_h(v0, v1);
                    } else {
                        *(uint32_t*)(Vh + dst) = pack_round_h(v0, v1);
                    }
                }
            }
    } else {
#pragma unroll
        for (int mt = 0; mt < 4; ++mt)
#pragma unroll
            for (int j = 0; j < 4; ++j) {
                size_t row = bm + wm * 64 + mt * 16 + r0;
                size_t col = bn + wn * 32 + j * 8 + c0;
                float bx = 0.f, by = 0.f;
                if (bias) { bx = bias[col]; by = bias[col + 1]; }
                float2 v0 = {c[mt][j][0] + bx, c[mt][j][1] + by};
                float2 v1 = {c[mt][j][2] + bx, c[mt][j][3] + by};
                *(float2*)(C + row * (size_t)N + col) = v0;
                *(float2*)(C + (row + 8) * (size_t)N + col) = v1;
            }
    }
}

// ------------------- fp16 HMMA flash attention (hi branch) -------------------
// KV stage: Kh + Vh = 16KB; Q split fp16x2 in fragments; P split in registers.
#define ATT_SMEM (2 * 16384 + 1024)

__global__ __launch_bounds__(128) void hi_attn_mma(
    const h16* __restrict__ Qh, const h16* __restrict__ Ql,
    const h16* __restrict__ Kh, const h16* __restrict__ Vh,
    float* __restrict__ out) {
    extern __shared__ char dynsm[];
    const int tid = threadIdx.x;
    const int wid = tid >> 5, lane = tid & 31;
    const int qt = blockIdx.x, h = blockIdx.y, b = blockIdx.z;
    const uint32_t sb = (smem_u32(dynsm) + 1023) & ~1023u;
    const size_t bh = (size_t)(b * 8 + h) * 65536;

    const int sub = lane >> 3;
    const int rowl = ((sub & 1) << 3) + (lane & 7);
    const int csel = sub >> 1;

    {
        const char* qh_src = (const char*)(Qh + bh + (size_t)qt * 64 * 64);
        const char* ql_src = (const char*)(Ql + bh + (size_t)qt * 64 * 64);
#pragma unroll
        for (int u = tid; u < 512; u += 128) {
            cp16(sb + sw128(u * 16), qh_src + u * 16);
            cp16(sb + 8192 + sw128(u * 16), ql_src + u * 16);
        }
        asm volatile("cp.async.commit_group;" ::: "memory");
        asm volatile("cp.async.wait_group 0;" ::: "memory");
        __syncthreads();
    }
    uint32_t qh[4][4], ql[4][4];
#pragma unroll
    for (int kf = 0; kf < 4; ++kf) {
        uint32_t off = (uint32_t)(wid * 16 + rowl) * 128 + kf * 32 + csel * 16;
        LDSM4(qh[kf], sb + sw128(off));
        LDSM4(ql[kf], sb + 8192 + sw128(off));
    }
    __syncthreads();

    const char* kh_src = (const char*)(Kh + bh);
    const char* vh_src = (const char*)(Vh + bh);

    auto load_kv = [&](int kt, int s) {
        const uint32_t base = sb + s * 16384;
        const size_t go = (size_t)kt * 8192;
#pragma unroll
        for (int u = tid; u < 512; u += 128) {
            uint32_t sw = sw128(u * 16);
            cp16(base + sw, kh_src + go + u * 16);
            cp16(base + 8192 + sw, vh_src + go + u * 16);
        }
        asm volatile("cp.async.commit_group;" ::: "memory");
    };

    load_kv(0, 0);
    load_kv(1, 1);

    float o[8][4];
#pragma unroll
    for (int i = 0; i < 8; ++i)
#pragma unroll
        for (int j = 0; j < 4; ++j) o[i][j] = 0.f;
    float m0 = -1e30f, m1 = -1e30f, l0 = 0.f, l1 = 0.f;

#pragma unroll 1
    for (int kt = 0; kt < 16; ++kt) {
        const int s = kt & 1;
        if (kt < 15) asm volatile("cp.async.wait_group 1;" ::: "memory");
        else         asm volatile("cp.async.wait_group 0;" ::: "memory");
        __syncthreads();
        const uint32_t base = sb + s * 16384;

        float sfr[8][4];
#pragma unroll
        for (int i = 0; i < 8; ++i)
#pragma unroll
            for (int j = 0; j < 4; ++j) sfr[i][j] = 0.f;

#pragma unroll
        for (int kf = 0; kf < 4; ++kf) {
            uint32_t kbh[4][4];
#pragma unroll
            for (int nb = 0; nb < 4; ++nb) {
                uint32_t off = (uint32_t)(nb * 16 + rowl) * 128 + kf * 32 + csel * 16;
                LDSM4(kbh[nb], base + sw128(off));
            }
#pragma unroll
            for (int nb = 0; nb < 4; ++nb) {
                MMA16816(sfr[nb * 2], qh[kf], kbh[nb][0], kbh[nb][2]);
                MMA16816(sfr[nb * 2 + 1], qh[kf], kbh[nb][1], kbh[nb][3]);
            }
#pragma unroll
            for (int nb = 0; nb < 4; ++nb) {
                MMA16816(sfr[nb * 2], ql[kf], kbh[nb][0], kbh[nb][2]);
                MMA16816(sfr[nb * 2 + 1], ql[kf], kbh[nb][1], kbh[nb][3]);
            }
        }

        float mx0 = -1e30f, mx1 = -1e30f;
#pragma unroll
        for (int n8 = 0; n8 < 8; ++n8) {
            mx0 = fmaxf(mx0, fmaxf(sfr[n8][0], sfr[n8][1]));
            mx1 = fmaxf(mx1, fmaxf(sfr[n8][2], sfr[n8][3]));
        }
        mx0 = fmaxf(mx0, __shfl_xor_sync(0xffffffffu, mx0, 1));
        mx0 = fmaxf(mx0, __shfl_xor_sync(0xffffffffu, mx0, 2));
        mx1 = fmaxf(mx1, __shfl_xor_sync(0xffffffffu, mx1, 1));
        mx1 = fmaxf(mx1, __shfl_xor_sync(0xffffffffu, mx1, 2));
        float m0n = fmaxf(m0, mx0), m1n = fmaxf(m1, mx1);
        float c0 = __expf(m0 - m0n), c1 = __expf(m1 - m1n);
        m0 = m0n; m1 = m1n;
        float s0 = 0.f, s1 = 0.f;
#pragma unroll
        for (int n8 = 0; n8 < 8; ++n8) {
            sfr[n8][0] = __expf(sfr[n8][0] - m0n);
            sfr[n8][1] = __expf(sfr[n8][1] - m0n);
            sfr[n8][2] = __expf(sfr[n8][2] - m1n);
            sfr[n8][3] = __expf(sfr[n8][3] - m1n);
            s0 += sfr[n8][0] + sfr[n8][1];
            s1 += sfr[n8][2] + sfr[n8][3];
        }
        s0 += __shfl_xor_sync(0xffffffffu, s0, 1);
        s0 += __shfl_xor_sync(0xffffffffu, s0, 2);
        s1 += __shfl_xor_sync(0xffffffffu, s1, 1);
        s1 += __shfl_xor_sync(0xffffffffu, s1, 2);
        l0 = l0 * c0 + s0;
        l1 = l1 * c1 + s1;
#pragma unroll
        for (int n8 = 0; n8 < 8; ++n8) {
            o[n8][0] *= c0; o[n8][1] *= c0;
            o[n8][2] *= c1; o[n8][3] *= c1;
        }

#pragma unroll
        for (int kf = 0; kf < 4; ++kf) {
            uint32_t ah4[4], al4[4];
            pack_split_h(sfr[2 * kf][0], sfr[2 * kf][1], &ah4[0], &al4[0]);
            pack_split_h(sfr[2 * kf][2], sfr[2 * kf][3], &ah4[1], &al4[1]);
            pack_split_h(sfr[2 * kf + 1][0], sfr[2 * kf + 1][1], &ah4[2], &al4[2]);
            pack_split_h(sfr[2 * kf + 1][2], sfr[2 * kf + 1][3], &ah4[3], &al4[3]);
            uint32_t vbh[4][4];
#pragma unroll
            for (int dd = 0; dd < 4; ++dd) {
                uint32_t off = (uint32_t)(kf * 16 + rowl) * 128 + dd * 32 + csel * 16;
                LDSM4T(vbh[dd], base + 8192 + sw128(off));
            }
#pragma unroll
            for (int dd = 0; dd < 4; ++dd) {
                MMA16816(o[dd * 2], ah4, vbh[dd][0], vbh[dd][1]);
                MMA16816(o[dd * 2 + 1], ah4, vbh[dd][2], vbh[dd][3]);
            }
#pragma unroll
            for (int dd = 0; dd < 4; ++dd) {
                MMA16816(o[dd * 2], al4, vbh[dd][0], vbh[dd][1]);
                MMA16816(o[dd * 2 + 1], al4, vbh[dd][2], vbh[dd][3]);
            }
        }
        __syncthreads();
        if (kt + 2 < 16) load_kv(kt + 2, s);
    }

    float inv0 = 1.0f / l0, inv1 = 1.0f / l1;
    int r0 = lane >> 2, cc = (lane & 3) * 2;
    size_t row = (size_t)(b * 1024 + qt * 64 + wid * 16 + r0);
#pragma unroll
    for (int n8 = 0; n8 < 8; ++n8) {
        size_t col = h * 64 + n8 * 8 + cc;
        float2 v0 = {o[n8][0] * inv0, o[n8][1] * inv0};
        float2 v1 = {o[n8][2] * inv1, o[n8][3] * inv1};
        *(float2*)(out + row * 512 + col) = v0;
        *(float2*)(out + (row + 8) * 512 + col) = v1;
    }
}

// ----------------------------- lo attention ---------------------------------
__global__ __launch_bounds__(256) void lo_attn_kernel(const float* __restrict__ qkv,
                                                      float* __restrict__ acc) {
    int gw = (blockIdx.x * 256 + threadIdx.x) >> 5;
    int lane = threadIdx.x & 31;
    int h = gw & 7;
    int w = (gw >> 3) & 1023;
    int b = gw >> 13;
    const float* base = qkv + (size_t)(b * 4096 + w * 4) * 1536 + h * 64 + lane;
    float q[4][2], k[4][2], v[4][2];
#pragma unroll
    for (int t = 0; t < 4; ++t) {
        const float* r = base + t * 1536;
        q[t][0] = r[0];    q[t][1] = r[32];
        k[t][0] = r[512];  k[t][1] = r[544];
        v[t][0] = r[1024]; v[t][1] = r[1056];
    }
    float lg[4][4];
#pragma unroll
    for (int t = 0; t < 4; ++t)
#pragma unroll
        for (int s2 = 0; s2 < 4; ++s2)
            lg[t][s2] = q[t][0] * k[s2][0] + q[t][1] * k[s2][1];
#pragma unroll
    for (int off = 16; off; off >>= 1)
#pragma unroll
        for (int t = 0; t < 4; ++t)
#pragma unroll
            for (int s2 = 0; s2 < 4; ++s2)
                lg[t][s2] += __shfl_xor_sync(0xffffffffu, lg[t][s2], off);

    int hh = w >> 5, wh = w & 31;
#pragma unroll
    for (int t = 0; t < 4; ++t) {
        float L0 = lg[t][0] * 0.125f, L1 = lg[t][1] * 0.125f;
        float L2 = lg[t][2] * 0.125f, L3 = lg[t][3] * 0.125f;
        float m = fmaxf(fmaxf(L0, L1), fmaxf(L2, L3));
        float p0 = __expf(L0 - m), p1 = __expf(L1 - m);
        float p2 = __expf(L2 - m), p3 = __expf(L3 - m);
        float inv = 1.0f / (p0 + p1 + p2 + p3);
        float o0 = (p0 * v[0][0] + p1 * v[1][0] + p2 * v[2][0] + p3 * v[3][0]) * inv;
        float o1 = (p0 * v[0][1] + p1 * v[1][1] + p2 * v[2][1] + p3 * v[3][1]) * inv;
        int tok = (hh * 2 + (t >> 1)) * 64 + wh * 2 + (t & 1);
        float* op = acc + (size_t)(b * 4096 + tok) * 512 + h * 64 + lane;
        op[0] = o0;
        op[32] = o1;
    }
}

// --------- bilinear upsample + add -> fp16 hi/lo split (vectorized) ----------
__global__ __launch_bounds__(256) void upsample_add_kernel(const float* __restrict__ hi,
                                                           const float* __restrict__ acc,
                                                           h16* __restrict__ ph,
                                                           h16* __restrict__ pl) {
    int g = blockIdx.x * 256 + threadIdx.x;
    if (g >= 8 * 4096 * 128) return;
    int c = (g & 127) * 4;
    int tok = (g >> 7) & 4095;
    int b = g >> 19;
    int y = tok >> 6, x = tok & 63;
    float fy = 0.5f * y - 0.25f;
    float fx = 0.5f * x - 0.25f;
    int y0 = (int)floorf(fy);
    int x0 = (int)floorf(fx);
    float wy = fy - (float)y0;
    float wx = fx - (float)x0;
    int y0c = max(y0, 0), y1c = min(y0 + 1, 31);
    int x0c = max(x0, 0), x1c = min(x0 + 1, 31);
    const float* hp = hi + (size_t)b * 1024 * 512 + c;
    float4 v00 = *(const float4*)(hp + (size_t)(y0c * 32 + x0c) * 512);
    float4 v01 = *(const float4*)(hp + (size_t)(y0c * 32 + x1c) * 512);
    float4 v10 = *(const float4*)(hp + (size_t)(y1c * 32 + x0c) * 512);
    float4 v11 = *(const float4*)(hp + (size_t)(y1c * 32 + x1c) * 512);
    float w00 = (1.f - wy) * (1.f - wx), w01 = (1.f - wy) * wx;
    float w10 = wy * (1.f - wx), w11 = wy * wx;
    size_t idx = ((size_t)(b * 4096 + tok)) * 512 + c;
    float4 a = *(const float4*)(acc + idx);
    float4 r;
    r.x = a.x + w00 * v00.x + w01 * v01.x + w10 * v10.x + w11 * v11.x;
    r.y = a.y + w00 * v00.y + w01 * v01.y + w10 * v10.y + w11 * v11.y;
    r.z = a.z + w00 * v00.z + w01 * v01.z + w10 * v10.z + w11 * v11.z;
    r.w = a.w + w00 * v00.w + w01 * v01.w + w10 * v10.w + w11 * v11.w;
    split4_store(r, ph, pl, idx);
}

// --------------------------------- launch -----------------------------------
extern "C" void kernel_launch(void* const* d_in, const int* in_sizes, int n_in,
                              void* d_out, int out_size) {
    const float* x     = (const float*)d_in[0];
    const float* Wqkv  = (const float*)d_in[1];
    const float* Wproj = (const float*)d_in[2];
    const float* bproj = (const float*)d_in[3];
    float* out = (float*)d_out;

    h16 *Ahi, *Alo, *Wqh, *Wph, *Phi, *Plo, *Qh, *Ql, *Kh, *Vh;
    float *qcat, *ahi, *acc;
    cudaGetSymbolAddress((void**)&Ahi, g_Ahi);
    cudaGetSymbolAddress((void**)&Alo, g_Alo);
    cudaGetSymbolAddress((void**)&Wqh, g_Wqh);
    cudaGetSymbolAddress((void**)&Wph, g_Wph);
    cudaGetSymbolAddress((void**)&Phi, g_Phi);
    cudaGetSymbolAddress((void**)&Plo, g_Plo);
    cudaGetSymbolAddress((void**)&qcat, g_qcat);
    cudaGetSymbolAddress((void**)&ahi, g_ahi);
    cudaGetSymbolAddress((void**)&acc, g_acc);
    cudaGetSymbolAddress((void**)&Qh, g_Qh);
    cudaGetSymbolAddress((void**)&Ql, g_Ql);
    cudaGetSymbolAddress((void**)&Kh, g_Kh);
    cudaGetSymbolAddress((void**)&Vh, g_Vh);

    cudaFuncSetAttribute((const void*)gemm_mma,
                         cudaFuncAttributeMaxDynamicSharedMemorySize, GEMM_SMEM);
    cudaFuncSetAttribute((const void*)hi_attn_mma,
                         cudaFuncAttributeMaxDynamicSharedMemorySize, ATT_SMEM);

    prep_kernel<<<8192, 128>>>(x, Ahi, Alo);
    round_kernel<<<768, 256>>>(Wqkv, Wqh, 1536 * 512 / 4);
    round_kernel<<<256, 256>>>(Wproj, Wph, 512 * 512 / 4);

    gemm_mma<<<dim3(12, 320), 256, GEMM_SMEM>>>(Ahi, Alo, Wqh, nullptr,
                                                qcat, 1536, 1, Qh, Ql, Kh, Vh);

    hi_attn_mma<<<dim3(16, 8, 8), 128, ATT_SMEM>>>(Qh, Ql, Kh, Vh, ahi);
    lo_attn_kernel<<<8192, 256>>>(qcat + (size_t)8192 * 1536, acc);
    upsample_add_kernel<<<16384, 256>>>(ahi, acc, Phi, Plo);

    gemm_mma<<<dim3(4, 256), 256, GEMM_SMEM>>>(Phi, Plo, Wph, bproj,
                                               out, 512, 0,
                                               nullptr, nullptr, nullptr, nullptr);
}